// round 16
// baseline (speedup 1.0000x reference)
#include <cuda_runtime.h>
#include <cuda_bf16.h>
#include <math.h>
#include <stdio.h>
#include <stdint.h>

// Dims
#define BHN 32
#define TD 1024
#define SD 1024
#define HCD 128
#define QTILE 16           // q rows per CTA (K1)
#define NCH 8              // S chunks of 128 (K1)
#define THREADS1 256       // K1 threads (8 warps) -> 2 CTAs/SM
#define N_ELEM (BHN * TD * HCD)

// K1 smem layout (3 K-buffers for 2-CTA occupancy)
#define QS 136             // q tile row stride, bf16
#define KS 136             // k tile row stride, bf16
#define KVBUF (128 * KS * 2)                      // 34,816 per buffer
#define SMEM_QS (QTILE * QS * 2)                  // 4,352
#define SMEM_KV_OFF SMEM_QS
#define SMEM_RED_OFF (SMEM_QS + 3 * KVBUF)        // 108,800
#define SMEM_K1 (SMEM_RED_OFF + 1024)             // 109,824  (x2 = 219,648/SM)

// K2 (RV GEMM) config: 3-stage cp.async
#define TS2 72             // 64-col tile row stride, bf16
#define K2STAGE (2 * 128 * TS2 * 2)               // A+B per stage = 36,864
#define SMEM_K2 (3 * K2STAGE)                     // 110,592

// ------------- bf16 scratch (device globals) -------------------------------
__device__ __align__(128) __nv_bfloat16 g_kb[N_ELEM];    // [bh][s][c]
__device__ __align__(128) __nv_bfloat16 g_vtb[N_ELEM];   // [bh][c][s]
__device__ __align__(128) __nv_bfloat16 g_r[(size_t)BHN * TD * SD];  // [bh][t][s]

// ---------------- pre-pass dequant (K + VT in one launch) ------------------
__global__ __launch_bounds__(256)
void dequant2(const int* __restrict__ kq, const int* __restrict__ ksh,
              const int* __restrict__ vq, const int* __restrict__ vsh)
{
    const int* q = blockIdx.y ? vq : kq;
    const int* s = blockIdx.y ? vsh : ksh;
    __nv_bfloat16* out = blockIdx.y ? g_vtb : g_kb;
    int i = blockIdx.x * 256 + threadIdx.x;            // int4 index (exact grid)
    int4 v = ((const int4*)q)[i];
    int m = 1 << (s[i >> 1] & 31);
    __nv_bfloat16 o[4];
    o[0] = __float2bfloat16_rn((float)(v.x * m));
    o[1] = __float2bfloat16_rn((float)(v.y * m));
    o[2] = __float2bfloat16_rn((float)(v.z * m));
    o[3] = __float2bfloat16_rn((float)(v.w * m));
    ((uint2*)out)[i] = *(const uint2*)o;
}

__device__ __forceinline__ void mma16816(float c[4], const uint32_t a[4], const uint32_t b[2])
{
    asm volatile(
        "mma.sync.aligned.m16n8k16.row.col.f32.bf16.bf16.f32 "
        "{%0,%1,%2,%3}, {%4,%5,%6,%7}, {%8,%9}, {%0,%1,%2,%3};\n"
        : "+f"(c[0]), "+f"(c[1]), "+f"(c[2]), "+f"(c[3])
        : "r"(a[0]), "r"(a[1]), "r"(a[2]), "r"(a[3]), "r"(b[0]), "r"(b[1]));
}

__device__ __forceinline__ void ldsm_x4(uint32_t r[4], uint32_t addr)
{
    asm volatile("ldmatrix.sync.aligned.m8n8.x4.shared.b16 {%0,%1,%2,%3}, [%4];"
                 : "=r"(r[0]), "=r"(r[1]), "=r"(r[2]), "=r"(r[3]) : "r"(addr));
}

__device__ __forceinline__ uint32_t smem_u32(const void* p)
{
    return (uint32_t)__cvta_generic_to_shared(p);
}

__device__ __forceinline__ uint32_t f2bf2(float lo, float hi)
{
    __nv_bfloat162 h = __floats2bfloat162_rn(lo, hi);
    return *(uint32_t*)&h;
}

#define CPA16(dst, srcp) \
    asm volatile("cp.async.cg.shared.global [%0], [%1], 16;\n" :: "r"(dst), "l"(srcp))
#define CPA_COMMIT() asm volatile("cp.async.commit_group;\n" ::: "memory")
template <int N>
__device__ __forceinline__ void cp_wait()
{
    asm volatile("cp.async.wait_group %0;\n" :: "n"(N));
}

// ============================ K1: QK + softmax + requant ====================
// 16 q-rows per CTA, scores fully register-resident (64 f32/thread), 2 CTAs/SM.
__global__ __launch_bounds__(THREADS1, 2)
void qk_softmax(const int* __restrict__ qq, const int* __restrict__ qsh)
{
    extern __shared__ char sm[];
    __nv_bfloat16* Qs   = (__nv_bfloat16*)sm;               // 16 x QS
    char*          Kv   = sm + SMEM_KV_OFF;                  // 3 x (128 x KS)
    float*         redM = (float*)(sm + SMEM_RED_OFF);       // [16][8]
    float*         redS = redM + 128;                        // [16][8]

    const int bh   = blockIdx.y;
    const int t0   = blockIdx.x * QTILE;
    const int tid  = threadIdx.x;
    const int lane = tid & 31;
    const int wn   = tid >> 5;          // warp 0..7: 16-col slice per chunk
    const int fr   = lane >> 2;         // fragment row 0..7
    const int fc   = (lane & 3) << 1;   // fragment col {0,2,4,6}

    const uint32_t aQ  = smem_u32(&Qs[(lane & 15) * QS + ((lane >> 4) << 3)]);
    const uint32_t bKV = smem_u32(Kv)
        + ((wn * 16 + (lane & 7) + ((lane >> 4) << 3)) * KS + (((lane >> 3) & 1) << 3)) * 2;

    const __nv_bfloat16* Kg = g_kb + (size_t)bh * SD * HCD;

#define LOADK(CH, BUF)                                                        \
    {                                                                         \
        const __nv_bfloat16* src = Kg + (size_t)(CH) * 128 * HCD;             \
        uint32_t base = smem_u32(Kv) + (BUF) * KVBUF;                         \
        _Pragma("unroll")                                                     \
        for (int i = 0; i < 8; i++) {                                         \
            int u = tid + i * THREADS1;                                       \
            int row = u >> 4, seg = u & 15;                                   \
            CPA16(base + (row * KS + seg * 8) * 2,                            \
                  src + (size_t)row * HCD + seg * 8);                         \
        }                                                                     \
        CPA_COMMIT();                                                         \
    }

    // prologue: start K pipeline, then inline-dequant q tile (16 x 128)
    LOADK(0, 0);
    LOADK(1, 1);
    {
        const int* qb = qq  + ((size_t)bh * TD + t0) * HCD;
        const int* sb = qsh + ((size_t)bh * TD + t0) * 16;
#pragma unroll
        for (int i = 0; i < 2; i++) {                      // 512 int4 / 256 thr
            int u = tid + i * THREADS1;
            int row = u >> 5, c4 = u & 31;
            int4 v = *(const int4*)(qb + (size_t)row * HCD + c4 * 4);
            int m = 1 << (sb[row * 16 + (c4 >> 1)] & 31);
            __nv_bfloat16 o[4];
            o[0] = __float2bfloat16_rn((float)(v.x * m));
            o[1] = __float2bfloat16_rn((float)(v.y * m));
            o[2] = __float2bfloat16_rn((float)(v.z * m));
            o[3] = __float2bfloat16_rn((float)(v.w * m));
            *(uint2*)&Qs[row * QS + c4 * 4] = *(const uint2*)o;
        }
    }

    uint32_t afq[8][4];
    float acc[8][2][4];
#pragma unroll
    for (int ch = 0; ch < 8; ch++)
#pragma unroll
        for (int nt = 0; nt < 2; nt++)
#pragma unroll
            for (int i = 0; i < 4; i++) acc[ch][nt][i] = 0.f;

#pragma unroll
    for (int ch = 0; ch < NCH; ch++) {
        if (ch < 7) cp_wait<1>(); else cp_wait<0>();
        __syncthreads();
        if (ch + 2 < NCH) LOADK(ch + 2, (ch + 2) % 3);
        if (ch == 0) {
#pragma unroll
            for (int ks = 0; ks < 8; ks++) ldsm_x4(afq[ks], aQ + ks * 32);
        }
        const uint32_t bB = bKV + (ch % 3) * KVBUF;
#pragma unroll
        for (int ks = 0; ks < 8; ks++) {
            uint32_t b[4];
            ldsm_x4(b, bB + ks * 32);
            mma16816(acc[ch][0], afq[ks], b);
            mma16816(acc[ch][1], afq[ks], b + 2);
        }
    }

    // -------- softmax + requant, fully register-resident --------------
    const float SCALE = (float)(6.103515625e-05 / sqrt(128.0)); // f32(2^-14/sqrt(HC))
    const int row0 = fr;
    const int row1 = fr + 8;

    // row maxima
    float m0 = -3.0e38f, m1 = -3.0e38f;
#pragma unroll
    for (int ch = 0; ch < 8; ch++)
#pragma unroll
        for (int nt = 0; nt < 2; nt++) {
            m0 = fmaxf(m0, fmaxf(acc[ch][nt][0], acc[ch][nt][1]));
            m1 = fmaxf(m1, fmaxf(acc[ch][nt][2], acc[ch][nt][3]));
        }
    m0 = fmaxf(m0, __shfl_xor_sync(0xffffffffu, m0, 1));
    m0 = fmaxf(m0, __shfl_xor_sync(0xffffffffu, m0, 2));
    m1 = fmaxf(m1, __shfl_xor_sync(0xffffffffu, m1, 1));
    m1 = fmaxf(m1, __shfl_xor_sync(0xffffffffu, m1, 2));
    if ((lane & 3) == 0) {
        redM[row0 * 8 + wn] = m0;
        redM[row1 * 8 + wn] = m1;
    }
    __syncthreads();
    float mx0 = -3.0e38f, mx1 = -3.0e38f;
#pragma unroll
    for (int j = 0; j < 8; j++) {
        mx0 = fmaxf(mx0, redM[row0 * 8 + j]);
        mx1 = fmaxf(mx1, redM[row1 * 8 + j]);
    }
    const float lm0 = mx0 * SCALE;
    const float lm1 = mx1 * SCALE;

    // exp + row sums (e overwrites acc)
    float s0 = 0.f, s1 = 0.f;
#pragma unroll
    for (int ch = 0; ch < 8; ch++)
#pragma unroll
        for (int nt = 0; nt < 2; nt++) {
            acc[ch][nt][0] = expf(acc[ch][nt][0] * SCALE - lm0);
            acc[ch][nt][1] = expf(acc[ch][nt][1] * SCALE - lm0);
            acc[ch][nt][2] = expf(acc[ch][nt][2] * SCALE - lm1);
            acc[ch][nt][3] = expf(acc[ch][nt][3] * SCALE - lm1);
            s0 += acc[ch][nt][0] + acc[ch][nt][1];
            s1 += acc[ch][nt][2] + acc[ch][nt][3];
        }
    s0 += __shfl_xor_sync(0xffffffffu, s0, 1);
    s0 += __shfl_xor_sync(0xffffffffu, s0, 2);
    s1 += __shfl_xor_sync(0xffffffffu, s1, 1);
    s1 += __shfl_xor_sync(0xffffffffu, s1, 2);
    if ((lane & 3) == 0) {
        redS[row0 * 8 + wn] = s0;
        redS[row1 * 8 + wn] = s1;
    }
    __syncthreads();
    float sum0 = 0.f, sum1 = 0.f;
#pragma unroll
    for (int j = 0; j < 8; j++) {
        sum0 += redS[row0 * 8 + j];
        sum1 += redS[row1 * 8 + j];
    }
    // one exact division per row; per-element becomes a single multiply
    const float rs0 = __fdiv_rn(16384.0f, sum0);
    const float rs1 = __fdiv_rn(16384.0f, sum1);

    // requant: group of 8 cols = 4 lanes x 2 vals (same fr quadrant)
    __nv_bfloat16* rout = g_r + ((size_t)bh * TD + t0) * SD;
#pragma unroll
    for (int ch = 0; ch < 8; ch++) {
#pragma unroll
        for (int nt = 0; nt < 2; nt++) {
            int col = ch * 128 + wn * 16 + nt * 8 + fc;
            // row0
            {
                float v0 = rintf(acc[ch][nt][0] * rs0);
                float v1 = rintf(acc[ch][nt][1] * rs0);
                float g = fmaxf(v0, v1);
                g = fmaxf(g, __shfl_xor_sync(0xffffffffu, g, 1));
                g = fmaxf(g, __shfl_xor_sync(0xffffffffu, g, 2));
                int gi = (int)g;                       // <= 16384
                int vv = (gi + 254) / 255;             // ceil(gi/255)
                int k  = (vv > 1) ? (32 - __clz(vv - 1)) : 0;
                float dn = __int_as_float((127 - k) << 23);   // exact 2^-k
                float up = __int_as_float((127 + k) << 23);   // exact 2^k
                float r0 = fminf(rintf(v0 * dn), 255.0f) * up;
                float r1 = fminf(rintf(v1 * dn), 255.0f) * up;
                *(uint32_t*)&rout[(size_t)row0 * SD + col] = f2bf2(r0, r1);
            }
            // row1
            {
                float v0 = rintf(acc[ch][nt][2] * rs1);
                float v1 = rintf(acc[ch][nt][3] * rs1);
                float g = fmaxf(v0, v1);
                g = fmaxf(g, __shfl_xor_sync(0xffffffffu, g, 1));
                g = fmaxf(g, __shfl_xor_sync(0xffffffffu, g, 2));
                int gi = (int)g;
                int vv = (gi + 254) / 255;
                int k  = (vv > 1) ? (32 - __clz(vv - 1)) : 0;
                float dn = __int_as_float((127 - k) << 23);
                float up = __int_as_float((127 + k) << 23);
                float r0 = fminf(rintf(v0 * dn), 255.0f) * up;
                float r1 = fminf(rintf(v1 * dn), 255.0f) * up;
                *(uint32_t*)&rout[(size_t)row1 * SD + col] = f2bf2(r0, r1);
            }
        }
    }
}

// ============================ K2: RV GEMM (3-stage) =========================
// out[bh][t][c] = r[bh][t][s] @ vt[bh][c][s]^T ; 128x128 tile, K=1024
__global__ __launch_bounds__(256, 2)
void rv_gemm(float* __restrict__ out)
{
    extern __shared__ char sm[];
    __nv_bfloat16* A0 = (__nv_bfloat16*)sm;         // stage: A(128xTS2) + B(128xTS2)
    __nv_bfloat16* B0 = A0 + 128 * TS2;

    const int bh  = blockIdx.y;
    const int m0  = blockIdx.x * 128;
    const int tid = threadIdx.x;
    const int lane = tid & 31;
    const int warp = tid >> 5;
    const int wm   = warp & 1;          // 64-row half
    const int wn   = warp >> 1;         // 0..3, 32-col slice
    const int fr   = lane >> 2;
    const int fc   = (lane & 3) << 1;

    const __nv_bfloat16* Ag = g_r   + (size_t)bh * TD * SD + (size_t)m0 * SD;
    const __nv_bfloat16* Bg = g_vtb + (size_t)bh * HCD * SD;

    const int lrow = tid >> 3;          // 0..31 (x4 iters -> 128 rows)
    const int lseg = tid & 7;           // 0..7

#define LOADCH(KC)                                                            \
    {                                                                         \
        uint32_t off = ((KC) % 3) * (uint32_t)K2STAGE;                        \
        uint32_t abase = smem_u32(A0) + off;                                  \
        uint32_t bbase = smem_u32(B0) + off;                                  \
        _Pragma("unroll")                                                     \
        for (int i = 0; i < 4; i++) {                                         \
            int row = lrow + i * 32;                                          \
            CPA16(abase + (row * TS2 + lseg * 8) * 2,                         \
                  Ag + (size_t)row * SD + (KC) * 64 + lseg * 8);              \
            CPA16(bbase + (row * TS2 + lseg * 8) * 2,                         \
                  Bg + (size_t)row * SD + (KC) * 64 + lseg * 8);              \
        }                                                                     \
        CPA_COMMIT();                                                         \
    }

    const uint32_t aA = smem_u32(A0)
        + ((wm * 64 + (lane & 15)) * TS2 + ((lane >> 4) << 3)) * 2;
    const uint32_t bB = smem_u32(B0)
        + ((wn * 32 + (lane & 7) + ((lane >> 4) << 3)) * TS2 + (((lane >> 3) & 1) << 3)) * 2;

    float acc[4][4][4];
#pragma unroll
    for (int mf = 0; mf < 4; mf++)
#pragma unroll
        for (int nt = 0; nt < 4; nt++)
#pragma unroll
            for (int i = 0; i < 4; i++) acc[mf][nt][i] = 0.f;

    LOADCH(0);
    LOADCH(1);

    for (int kc = 0; kc < 16; kc++) {
        if (kc + 2 < 16) {
            LOADCH(kc + 2);
            cp_wait<2>();
        } else if (kc + 2 == 16) {
            cp_wait<1>();
        } else {
            cp_wait<0>();
        }
        __syncthreads();

        const uint32_t boff = (kc % 3) * (uint32_t)K2STAGE;
#pragma unroll
        for (int ks = 0; ks < 4; ks++) {
            uint32_t a[4][4], b[2][4];
#pragma unroll
            for (int mf = 0; mf < 4; mf++)
                ldsm_x4(a[mf], aA + boff + mf * (16 * TS2 * 2) + ks * 32);
#pragma unroll
            for (int p = 0; p < 2; p++)
                ldsm_x4(b[p], bB + boff + p * (16 * TS2 * 2) + ks * 32);
#pragma unroll
            for (int mf = 0; mf < 4; mf++)
#pragma unroll
                for (int p = 0; p < 2; p++) {
                    mma16816(acc[mf][2 * p],     a[mf], b[p]);
                    mma16816(acc[mf][2 * p + 1], a[mf], b[p] + 2);
                }
        }
        __syncthreads();
    }

    float* C = out + (size_t)bh * TD * HCD;
#pragma unroll
    for (int mf = 0; mf < 4; mf++) {
#pragma unroll
        for (int nt = 0; nt < 4; nt++) {
            int row = m0 + wm * 64 + mf * 16 + fr;
            int col = wn * 32 + (nt >> 1) * 16 + (nt & 1) * 8 + fc;
            *(float2*)&C[(size_t)row * HCD + col] =
                make_float2(rintf(acc[mf][nt][0]), rintf(acc[mf][nt][1]));
            *(float2*)&C[(size_t)(row + 8) * HCD + col] =
                make_float2(rintf(acc[mf][nt][2]), rintf(acc[mf][nt][3]));
        }
    }
}

// ---------------------------------------------------------------------------
static void diag_sync(const char* stage)
{
    cudaStreamCaptureStatus st = cudaStreamCaptureStatusNone;
    cudaStreamIsCapturing(0, &st);
    if (st == cudaStreamCaptureStatusNone) {
        cudaError_t e = cudaStreamSynchronize(0);
        if (e != cudaSuccess)
            fprintf(stderr, "[kl] stage %s: %s\n", stage, cudaGetErrorString(e));
    }
}

extern "C" void kernel_launch(void* const* d_in, const int* in_sizes, int n_in,
                              void* d_out, int out_size)
{
    if (n_in < 6) { fprintf(stderr, "[kl] bad n_in=%d\n", n_in); return; }

    const int* qq  = (const int*)d_in[0];
    const int* qsh = (const int*)d_in[1];
    const int* kq  = (const int*)d_in[2];
    const int* ksh = (const int*)d_in[3];
    const int* vq  = (const int*)d_in[4];
    const int* vsh = (const int*)d_in[5];

    dim3 gd(N_ELEM / 4 / 256, 2);                   // 4096 x 2
    dequant2<<<gd, 256>>>(kq, ksh, vq, vsh);

    static int attr_done = 0;
    if (!attr_done) {
        cudaFuncSetAttribute(qk_softmax,
            cudaFuncAttributeMaxDynamicSharedMemorySize, SMEM_K1);
        cudaFuncSetAttribute(rv_gemm,
            cudaFuncAttributeMaxDynamicSharedMemorySize, SMEM_K2);
        attr_done = 1;
    }

    dim3 g1(TD / QTILE, BHN);     // 64 x 32 = 2048 CTAs, 2/SM
    qk_softmax<<<g1, THREADS1, SMEM_K1>>>(qq, qsh);

    dim3 g2(TD / 128, BHN);       // 8 x 32 = 256 CTAs
    rv_gemm<<<g2, 256, SMEM_K2>>>((float*)d_out);
    diag_sync("split");
}

// round 17
// speedup vs baseline: 1.0647x; 1.0647x over previous
#include <cuda_runtime.h>
#include <cuda_bf16.h>
#include <math.h>
#include <stdio.h>
#include <stdint.h>

// Dims
#define BHN 32
#define TD 1024
#define SD 1024
#define HCD 128
#define QTILE 32           // q rows per CTA (K1)
#define NCH 8              // S chunks of 128 (K1)
#define THREADS 512        // K1 threads
#define N_ELEM (BHN * TD * HCD)

// K1 smem layout (R15 shape: 4 K-buffers, 1 CTA/SM)
#define QS 136             // q tile row stride, bf16
#define KS 136             // k tile row stride, bf16
#define KVBUF (128 * KS * 2)                      // 34,816 per buffer
#define SMEM_QS 8704                              // 32*136*2
#define SMEM_KV_OFF SMEM_QS
#define SMEM_RED_OFF (SMEM_QS + 4 * KVBUF)        // 147,968
#define SMEM_K1 (SMEM_RED_OFF + 2048)             // 150,016

// K2 (RV GEMM) config: 3-stage cp.async
#define TS2 72             // 64-col tile row stride, bf16
#define K2STAGE (2 * 128 * TS2 * 2)               // A+B per stage = 36,864
#define SMEM_K2 (3 * K2STAGE)                     // 110,592

// ------------- bf16 scratch (device globals) -------------------------------
__device__ __align__(128) __nv_bfloat16 g_kb[N_ELEM];    // [bh][s][c]
__device__ __align__(128) __nv_bfloat16 g_vtb[N_ELEM];   // [bh][c][s]
__device__ __align__(128) __nv_bfloat16 g_r[(size_t)BHN * TD * SD];  // [bh][t][s]

// ---------------- pre-pass dequant (one tensor per launch) -----------------
__global__ __launch_bounds__(256)
void dequant_one(const int* __restrict__ q, const int* __restrict__ s, int which)
{
    __nv_bfloat16* out = which ? g_vtb : g_kb;
    int i = blockIdx.x * 256 + threadIdx.x;            // int4 index (exact grid)
    int4 v = ((const int4*)q)[i];
    int m = 1 << (s[i >> 1] & 31);
    __nv_bfloat16 o[4];
    o[0] = __float2bfloat16_rn((float)(v.x * m));
    o[1] = __float2bfloat16_rn((float)(v.y * m));
    o[2] = __float2bfloat16_rn((float)(v.z * m));
    o[3] = __float2bfloat16_rn((float)(v.w * m));
    ((uint2*)out)[i] = *(const uint2*)o;
}

__device__ __forceinline__ void mma16816(float c[4], const uint32_t a[4], const uint32_t b[2])
{
    asm volatile(
        "mma.sync.aligned.m16n8k16.row.col.f32.bf16.bf16.f32 "
        "{%0,%1,%2,%3}, {%4,%5,%6,%7}, {%8,%9}, {%0,%1,%2,%3};\n"
        : "+f"(c[0]), "+f"(c[1]), "+f"(c[2]), "+f"(c[3])
        : "r"(a[0]), "r"(a[1]), "r"(a[2]), "r"(a[3]), "r"(b[0]), "r"(b[1]));
}

__device__ __forceinline__ void ldsm_x4(uint32_t r[4], uint32_t addr)
{
    asm volatile("ldmatrix.sync.aligned.m8n8.x4.shared.b16 {%0,%1,%2,%3}, [%4];"
                 : "=r"(r[0]), "=r"(r[1]), "=r"(r[2]), "=r"(r[3]) : "r"(addr));
}

__device__ __forceinline__ uint32_t smem_u32(const void* p)
{
    return (uint32_t)__cvta_generic_to_shared(p);
}

__device__ __forceinline__ uint32_t f2bf2(float lo, float hi)
{
    __nv_bfloat162 h = __floats2bfloat162_rn(lo, hi);
    return *(uint32_t*)&h;
}

// r_shift = clip(ceil(log2(max(gi,1)/255)),0) without integer division.
// k = smallest k with gi <= 255<<k. For msb b >= 8: k = (b-7) + (gi > 255<<(b-7)).
__device__ __forceinline__ int rshift_k(int gi)
{
    if (gi <= 255) return 0;
    int b = 31 - __clz(gi);
    return (b - 7) + (gi > (255 << (b - 7)));
}

#define CPA16(dst, srcp) \
    asm volatile("cp.async.cg.shared.global [%0], [%1], 16;\n" :: "r"(dst), "l"(srcp))
#define CPA_COMMIT() asm volatile("cp.async.commit_group;\n" ::: "memory")
template <int N>
__device__ __forceinline__ void cp_wait()
{
    asm volatile("cp.async.wait_group %0;\n" :: "n"(N));
}

// ============================ K1: QK + softmax + requant ====================
// Scores live entirely in registers (acc[8][2][4] = 64 f32/thread).
__global__ __launch_bounds__(THREADS)
void qk_softmax(const int* __restrict__ qq, const int* __restrict__ qsh)
{
    extern __shared__ char sm[];
    __nv_bfloat16* Qs   = (__nv_bfloat16*)sm;               // 32 x QS
    char*          Kv   = sm + SMEM_KV_OFF;                  // 4 x (128 x KS)
    float*         redM = (float*)(sm + SMEM_RED_OFF);       // [32][8]
    float*         redS = redM + 256;                        // [32][8]

    const int bh   = blockIdx.y;
    const int t0   = blockIdx.x * QTILE;
    const int tid  = threadIdx.x;
    const int lane = tid & 31;
    const int wid  = tid >> 5;
    const int wm   = wid & 1;           // m-half (16 rows)
    const int wn   = wid >> 1;          // 0..7 (16-col slice per chunk)
    const int fr   = lane >> 2;         // fragment row 0..7
    const int fc   = (lane & 3) << 1;   // fragment col {0,2,4,6}

    const uint32_t aQ  = smem_u32(&Qs[(wm * 16 + (lane & 15)) * QS + ((lane >> 4) << 3)]);
    const uint32_t bKV = smem_u32(Kv)
        + ((wn * 16 + (lane & 7) + ((lane >> 4) << 3)) * KS + (((lane >> 3) & 1) << 3)) * 2;

    const __nv_bfloat16* Kg = g_kb + (size_t)bh * SD * HCD;

#define LOADK(CH, BUF)                                                        \
    {                                                                         \
        const __nv_bfloat16* src = Kg + (size_t)(CH) * 128 * HCD;             \
        uint32_t base = smem_u32(Kv) + (BUF) * KVBUF;                         \
        _Pragma("unroll")                                                     \
        for (int i = 0; i < 4; i++) {                                         \
            int u = tid + i * THREADS;                                        \
            int row = u >> 4, seg = u & 15;                                   \
            CPA16(base + (row * KS + seg * 8) * 2,                            \
                  src + (size_t)row * HCD + seg * 8);                         \
        }                                                                     \
        CPA_COMMIT();                                                         \
    }

    // prologue: start K pipeline, then inline-dequant q tile
    LOADK(0, 0);
    LOADK(1, 1);
    {
        const int* qb = qq  + ((size_t)bh * TD + t0) * HCD;
        const int* sb = qsh + ((size_t)bh * TD + t0) * 16;
#pragma unroll
        for (int i = 0; i < 2; i++) {                      // 1024 int4 / 512 thr
            int u = tid + i * THREADS;
            int row = u >> 5, c4 = u & 31;
            int4 v = *(const int4*)(qb + (size_t)row * HCD + c4 * 4);
            int m = 1 << (sb[row * 16 + (c4 >> 1)] & 31);
            __nv_bfloat16 o[4];
            o[0] = __float2bfloat16_rn((float)(v.x * m));
            o[1] = __float2bfloat16_rn((float)(v.y * m));
            o[2] = __float2bfloat16_rn((float)(v.z * m));
            o[3] = __float2bfloat16_rn((float)(v.w * m));
            *(uint2*)&Qs[row * QS + c4 * 4] = *(const uint2*)o;
        }
    }
    LOADK(2, 2);
    cp_wait<2>();                      // group 0 complete
    __syncthreads();                   // Qs + Kv buf0 visible

    uint32_t afq[8][4];
#pragma unroll
    for (int ks = 0; ks < 8; ks++) ldsm_x4(afq[ks], aQ + ks * 32);

    float acc[8][2][4];
#pragma unroll
    for (int ch = 0; ch < 8; ch++)
#pragma unroll
        for (int nt = 0; nt < 2; nt++)
#pragma unroll
            for (int i = 0; i < 4; i++) acc[ch][nt][i] = 0.f;

#pragma unroll
    for (int ch = 0; ch < NCH; ch++) {
        if (ch > 0) {
            if (ch <= 5)      cp_wait<2>();
            else if (ch == 6) cp_wait<1>();
            else              cp_wait<0>();
            __syncthreads();
        }
        const uint32_t bB = bKV + (ch & 3) * KVBUF;
#pragma unroll
        for (int ks = 0; ks < 8; ks++) {
            uint32_t b[4];
            ldsm_x4(b, bB + ks * 32);
            mma16816(acc[ch][0], afq[ks], b);
            mma16816(acc[ch][1], afq[ks], b + 2);
        }
        if (ch + 3 < NCH) LOADK(ch + 3, (ch + 3) & 3);
    }

    // -------- softmax + requant, fully register-resident --------------
    const float SCALE = (float)(6.103515625e-05 / sqrt(128.0)); // f32(2^-14/sqrt(HC))
    const int row0 = wm * 16 + fr;
    const int row1 = row0 + 8;

    // row maxima
    float m0 = -3.0e38f, m1 = -3.0e38f;
#pragma unroll
    for (int ch = 0; ch < 8; ch++)
#pragma unroll
        for (int nt = 0; nt < 2; nt++) {
            m0 = fmaxf(m0, fmaxf(acc[ch][nt][0], acc[ch][nt][1]));
            m1 = fmaxf(m1, fmaxf(acc[ch][nt][2], acc[ch][nt][3]));
        }
    m0 = fmaxf(m0, __shfl_xor_sync(0xffffffffu, m0, 1));
    m0 = fmaxf(m0, __shfl_xor_sync(0xffffffffu, m0, 2));
    m1 = fmaxf(m1, __shfl_xor_sync(0xffffffffu, m1, 1));
    m1 = fmaxf(m1, __shfl_xor_sync(0xffffffffu, m1, 2));
    if ((lane & 3) == 0) {
        redM[row0 * 8 + wn] = m0;
        redM[row1 * 8 + wn] = m1;
    }
    __syncthreads();
    float mx0 = -3.0e38f, mx1 = -3.0e38f;
#pragma unroll
    for (int j = 0; j < 8; j++) {
        mx0 = fmaxf(mx0, redM[row0 * 8 + j]);
        mx1 = fmaxf(mx1, redM[row1 * 8 + j]);
    }
    const float lm0 = mx0 * SCALE;
    const float lm1 = mx1 * SCALE;

    // exp + row sums (e overwrites acc)
    float s0 = 0.f, s1 = 0.f;
#pragma unroll
    for (int ch = 0; ch < 8; ch++)
#pragma unroll
        for (int nt = 0; nt < 2; nt++) {
            acc[ch][nt][0] = expf(acc[ch][nt][0] * SCALE - lm0);
            acc[ch][nt][1] = expf(acc[ch][nt][1] * SCALE - lm0);
            acc[ch][nt][2] = expf(acc[ch][nt][2] * SCALE - lm1);
            acc[ch][nt][3] = expf(acc[ch][nt][3] * SCALE - lm1);
            s0 += acc[ch][nt][0] + acc[ch][nt][1];
            s1 += acc[ch][nt][2] + acc[ch][nt][3];
        }
    s0 += __shfl_xor_sync(0xffffffffu, s0, 1);
    s0 += __shfl_xor_sync(0xffffffffu, s0, 2);
    s1 += __shfl_xor_sync(0xffffffffu, s1, 1);
    s1 += __shfl_xor_sync(0xffffffffu, s1, 2);
    if ((lane & 3) == 0) {
        redS[row0 * 8 + wn] = s0;
        redS[row1 * 8 + wn] = s1;
    }
    __syncthreads();
    float sum0 = 0.f, sum1 = 0.f;
#pragma unroll
    for (int j = 0; j < 8; j++) {
        sum0 += redS[row0 * 8 + j];
        sum1 += redS[row1 * 8 + j];
    }
    // one exact division per row; per-element becomes a single multiply
    const float rs0 = __fdiv_rn(16384.0f, sum0);
    const float rs1 = __fdiv_rn(16384.0f, sum1);

    // requant: group of 8 cols = 4 lanes x 2 vals (same fr quadrant).
    // Both rows' group maxima packed into one 2x16-bit word -> single shuffle chain.
    __nv_bfloat16* rout = g_r + ((size_t)bh * TD + t0) * SD;
#pragma unroll
    for (int ch = 0; ch < 8; ch++) {
#pragma unroll
        for (int nt = 0; nt < 2; nt++) {
            int col = ch * 128 + wn * 16 + nt * 8 + fc;
            float v00 = rintf(acc[ch][nt][0] * rs0);   // row0 pair
            float v01 = rintf(acc[ch][nt][1] * rs0);
            float v10 = rintf(acc[ch][nt][2] * rs1);   // row1 pair
            float v11 = rintf(acc[ch][nt][3] * rs1);
            int p = (int)fmaxf(v00, v01) | ((int)fmaxf(v10, v11) << 16); // <=16384 fits s16
            p = __vmaxs2(p, __shfl_xor_sync(0xffffffffu, p, 1));
            p = __vmaxs2(p, __shfl_xor_sync(0xffffffffu, p, 2));
            int k0 = rshift_k(p & 0xffff);
            int k1 = rshift_k((int)((uint32_t)p >> 16));
            float dn0 = __int_as_float((127 - k0) << 23);   // exact 2^-k
            float up0 = __int_as_float((127 + k0) << 23);   // exact 2^k
            float dn1 = __int_as_float((127 - k1) << 23);
            float up1 = __int_as_float((127 + k1) << 23);
            float r00 = fminf(rintf(v00 * dn0), 255.0f) * up0;
            float r01 = fminf(rintf(v01 * dn0), 255.0f) * up0;
            float r10 = fminf(rintf(v10 * dn1), 255.0f) * up1;
            float r11 = fminf(rintf(v11 * dn1), 255.0f) * up1;
            *(uint32_t*)&rout[(size_t)row0 * SD + col] = f2bf2(r00, r01);
            *(uint32_t*)&rout[(size_t)row1 * SD + col] = f2bf2(r10, r11);
        }
    }
}

// ============================ K2: RV GEMM (3-stage) =========================
// out[bh][t][c] = r[bh][t][s] @ vt[bh][c][s]^T ; 128x128 tile, K=1024
__global__ __launch_bounds__(256, 2)
void rv_gemm(float* __restrict__ out)
{
    extern __shared__ char sm[];
    __nv_bfloat16* A0 = (__nv_bfloat16*)sm;         // stage: A(128xTS2) + B(128xTS2)
    __nv_bfloat16* B0 = A0 + 128 * TS2;

    const int bh  = blockIdx.y;
    const int m0  = blockIdx.x * 128;
    const int tid = threadIdx.x;
    const int lane = tid & 31;
    const int warp = tid >> 5;
    const int wm   = warp & 1;          // 64-row half
    const int wn   = warp >> 1;         // 0..3, 32-col slice
    const int fr   = lane >> 2;
    const int fc   = (lane & 3) << 1;

    const __nv_bfloat16* Ag = g_r   + (size_t)bh * TD * SD + (size_t)m0 * SD;
    const __nv_bfloat16* Bg = g_vtb + (size_t)bh * HCD * SD;

    const int lrow = tid >> 3;          // 0..31 (x4 iters -> 128 rows)
    const int lseg = tid & 7;           // 0..7

#define LOADCH(KC)                                                            \
    {                                                                         \
        uint32_t off = ((KC) % 3) * (uint32_t)K2STAGE;                        \
        uint32_t abase = smem_u32(A0) + off;                                  \
        uint32_t bbase = smem_u32(B0) + off;                                  \
        _Pragma("unroll")                                                     \
        for (int i = 0; i < 4; i++) {                                         \
            int row = lrow + i * 32;                                          \
            CPA16(abase + (row * TS2 + lseg * 8) * 2,                         \
                  Ag + (size_t)row * SD + (KC) * 64 + lseg * 8);              \
            CPA16(bbase + (row * TS2 + lseg * 8) * 2,                         \
                  Bg + (size_t)row * SD + (KC) * 64 + lseg * 8);              \
        }                                                                     \
        CPA_COMMIT();                                                         \
    }

    const uint32_t aA = smem_u32(A0)
        + ((wm * 64 + (lane & 15)) * TS2 + ((lane >> 4) << 3)) * 2;
    const uint32_t bB = smem_u32(B0)
        + ((wn * 32 + (lane & 7) + ((lane >> 4) << 3)) * TS2 + (((lane >> 3) & 1) << 3)) * 2;

    float acc[4][4][4];
#pragma unroll
    for (int mf = 0; mf < 4; mf++)
#pragma unroll
        for (int nt = 0; nt < 4; nt++)
#pragma unroll
            for (int i = 0; i < 4; i++) acc[mf][nt][i] = 0.f;

    LOADCH(0);
    LOADCH(1);

    for (int kc = 0; kc < 16; kc++) {
        if (kc + 2 < 16) {
            LOADCH(kc + 2);
            cp_wait<2>();
        } else if (kc + 2 == 16) {
            cp_wait<1>();
        } else {
            cp_wait<0>();
        }
        __syncthreads();

        const uint32_t boff = (kc % 3) * (uint32_t)K2STAGE;
#pragma unroll
        for (int ks = 0; ks < 4; ks++) {
            uint32_t a[4][4], b[2][4];
#pragma unroll
            for (int mf = 0; mf < 4; mf++)
                ldsm_x4(a[mf], aA + boff + mf * (16 * TS2 * 2) + ks * 32);
#pragma unroll
            for (int p = 0; p < 2; p++)
                ldsm_x4(b[p], bB + boff + p * (16 * TS2 * 2) + ks * 32);
#pragma unroll
            for (int mf = 0; mf < 4; mf++)
#pragma unroll
                for (int p = 0; p < 2; p++) {
                    mma16816(acc[mf][2 * p],     a[mf], b[p]);
                    mma16816(acc[mf][2 * p + 1], a[mf], b[p] + 2);
                }
        }
        __syncthreads();
    }

    float* C = out + (size_t)bh * TD * HCD;
#pragma unroll
    for (int mf = 0; mf < 4; mf++) {
#pragma unroll
        for (int nt = 0; nt < 4; nt++) {
            int row = m0 + wm * 64 + mf * 16 + fr;
            int col = wn * 32 + (nt >> 1) * 16 + (nt & 1) * 8 + fc;
            *(float2*)&C[(size_t)row * HCD + col] =
                make_float2(rintf(acc[mf][nt][0]), rintf(acc[mf][nt][1]));
            *(float2*)&C[(size_t)(row + 8) * HCD + col] =
                make_float2(rintf(acc[mf][nt][2]), rintf(acc[mf][nt][3]));
        }
    }
}

// ---------------------------------------------------------------------------
static void diag_sync(const char* stage)
{
    cudaStreamCaptureStatus st = cudaStreamCaptureStatusNone;
    cudaStreamIsCapturing(0, &st);
    if (st == cudaStreamCaptureStatusNone) {
        cudaError_t e = cudaStreamSynchronize(0);
        if (e != cudaSuccess)
            fprintf(stderr, "[kl] stage %s: %s\n", stage, cudaGetErrorString(e));
    }
}

extern "C" void kernel_launch(void* const* d_in, const int* in_sizes, int n_in,
                              void* d_out, int out_size)
{
    if (n_in < 6) { fprintf(stderr, "[kl] bad n_in=%d\n", n_in); return; }

    const int* qq  = (const int*)d_in[0];
    const int* qsh = (const int*)d_in[1];
    const int* kq  = (const int*)d_in[2];
    const int* ksh = (const int*)d_in[3];
    const int* vq  = (const int*)d_in[4];
    const int* vsh = (const int*)d_in[5];

    static cudaStream_t s2 = nullptr;
    static cudaEvent_t evF = nullptr, evJ = nullptr;
    static int attr_done = 0;
    if (!attr_done) {
        cudaFuncSetAttribute(qk_softmax,
            cudaFuncAttributeMaxDynamicSharedMemorySize, SMEM_K1);
        cudaFuncSetAttribute(rv_gemm,
            cudaFuncAttributeMaxDynamicSharedMemorySize, SMEM_K2);
        cudaStreamCreateWithFlags(&s2, cudaStreamNonBlocking);
        cudaEventCreateWithFlags(&evF, cudaEventDisableTiming);
        cudaEventCreateWithFlags(&evJ, cudaEventDisableTiming);
        attr_done = 1;
    }

    const int dblk = N_ELEM / 4 / 256;              // 4096
    const bool fork = (s2 && evF && evJ);

    if (fork) {
        // fork: V-dequant runs concurrently with K-dequant + K1
        cudaEventRecord(evF, 0);
        cudaStreamWaitEvent(s2, evF, 0);
        dequant_one<<<dblk, 256, 0, s2>>>(vq, vsh, 1);
        cudaEventRecord(evJ, s2);
    } else {
        dequant_one<<<dblk, 256>>>(vq, vsh, 1);
    }

    dequant_one<<<dblk, 256>>>(kq, ksh, 0);

    dim3 g1(TD / QTILE, BHN);     // 32 x 32
    qk_softmax<<<g1, THREADS, SMEM_K1>>>(qq, qsh);

    if (fork) cudaStreamWaitEvent(0, evJ, 0);       // join before RV

    dim3 g2(TD / 128, BHN);       // 8 x 32 = 256 CTAs
    rv_gemm<<<g2, 256, SMEM_K2>>>((float*)d_out);
    diag_sync("split");
}